// round 17
// baseline (speedup 1.0000x reference)
#include <cuda_runtime.h>
#include <cstdint>

// ---------------------------------------------------------------------------
// PrunedGroupSum: y[b,g] = (sum over contiguous column group g of x[b,:]) / 20
//   x:           [B, D] float32   (B=1024, D=262144 -> 1 GiB, streaming)
//   group_sizes: [K]    int32     (K=1000, sums to D)
//   out:         [B, K] float32
//
// R17: single fused kernel. Main body = R12 verbatim (best: 165.9us, DRAM
// 81.3% = the measured wall for this pattern; block = (group, 32 rows),
// warp = 8-row slice, unroll-2 -> 16 independent LDG.128, lb(128,5)).
// The separate prefix-scan kernel is eliminated: each warp computes its own
// (s, e) from the 4KB L2-resident group_sizes via a lane-parallel masked
// sum + butterfly reduce (~60 cycles, 0.03% of block lifetime).
// ---------------------------------------------------------------------------

#define ROWS_PER_WARP 8
#define ROWS_PER_BLOCK 32

__device__ __forceinline__ float hsum4(float4 v) {
    return (v.x + v.y) + (v.z + v.w);
}

__global__ __launch_bounds__(128, 5) void pgs_fused_kernel(
    const float* __restrict__ x,
    const int*   __restrict__ gsz,
    float* __restrict__ out,
    int D, int K, int B)
{
    int g = blockIdx.x;
    int warp = threadIdx.x >> 5;
    int lane = threadIdx.x & 31;

    int row0 = blockIdx.y * ROWS_PER_BLOCK + warp * ROWS_PER_WARP;
    int nrows = B - row0;
    if (nrows <= 0) return;
    if (nrows > ROWS_PER_WARP) nrows = ROWS_PER_WARP;

    // ---- per-warp offset computation: s = sum(gsz[0..g)), e = s + gsz[g] ----
    // K <= 1024. Lane l covers indices [32l, 32l+32) with 8 int4 loads
    // (gsz is 16B-aligned harness input), masked by idx < g.
    int s;
    {
        int partial = 0;
        int base = lane * 32;
#pragma unroll
        for (int i = 0; i < 32; i += 4) {
            int idx = base + i;
            if (idx < g) {                      // need any of idx..idx+3 < g
                if (idx + 3 < K) {
                    int4 t = *reinterpret_cast<const int4*>(gsz + idx);
                    partial += (idx     < g) ? t.x : 0;
                    partial += (idx + 1 < g) ? t.y : 0;
                    partial += (idx + 2 < g) ? t.z : 0;
                    partial += (idx + 3 < g) ? t.w : 0;
                } else {
#pragma unroll
                    for (int j = 0; j < 4; j++)
                        if (idx + j < g && idx + j < K) partial += gsz[idx + j];
                }
            }
        }
#pragma unroll
        for (int o = 16; o > 0; o >>= 1)
            partial += __shfl_xor_sync(0xffffffffu, partial, o);
        s = partial;
    }
    int e = s + gsz[g];

    const float* p = x + (size_t)row0 * (size_t)D;
    const size_t SD = (size_t)D;

    float acc[ROWS_PER_WARP];
#pragma unroll
    for (int r = 0; r < ROWS_PER_WARP; r++) acc[r] = 0.0f;

    int s4 = (s + 3) & ~3;
    int e4 = e & ~3;

    if (nrows == ROWS_PER_WARP) {
        if (s4 >= e4) {
            // tiny group: scalar, coalesced across lanes, 8 streams
            for (int c = s + lane; c < e; c += 32) {
#pragma unroll
                for (int r = 0; r < ROWS_PER_WARP; r++)
                    acc[r] += __ldcs(p + (size_t)r * SD + c);
            }
        } else {
            // head (<=3 scalar cols)
            {
                int c = s + lane;
                if (c < s4) {
#pragma unroll
                    for (int r = 0; r < ROWS_PER_WARP; r++)
                        acc[r] += __ldcs(p + (size_t)r * SD + c);
                }
            }
            int c4 = s4 + lane * 4;
            // unroll-2 main: 16 independent LDG.128 live at once
            for (; c4 + 128 < e4; c4 += 256) {
                float4 v[ROWS_PER_WARP];
                float4 w[ROWS_PER_WARP];
#pragma unroll
                for (int r = 0; r < ROWS_PER_WARP; r++)
                    v[r] = __ldcs(reinterpret_cast<const float4*>(p + (size_t)r * SD + c4));
#pragma unroll
                for (int r = 0; r < ROWS_PER_WARP; r++)
                    w[r] = __ldcs(reinterpret_cast<const float4*>(p + (size_t)r * SD + c4 + 128));
#pragma unroll
                for (int r = 0; r < ROWS_PER_WARP; r++)
                    acc[r] += hsum4(v[r]) + hsum4(w[r]);
            }
            // remainder vector tile (0 or 1 per lane)
            if (c4 < e4) {
                float4 v[ROWS_PER_WARP];
#pragma unroll
                for (int r = 0; r < ROWS_PER_WARP; r++)
                    v[r] = __ldcs(reinterpret_cast<const float4*>(p + (size_t)r * SD + c4));
#pragma unroll
                for (int r = 0; r < ROWS_PER_WARP; r++)
                    acc[r] += hsum4(v[r]);
            }
            // tail (<=3 scalar cols)
            {
                int c = e4 + lane;
                if (c < e) {
#pragma unroll
                    for (int r = 0; r < ROWS_PER_WARP; r++)
                        acc[r] += __ldcs(p + (size_t)r * SD + c);
                }
            }
        }
    } else {
        // remainder rows (B not multiple of 32): scalar per-row path
        for (int r = 0; r < nrows; r++) {
            const float* pr = p + (size_t)r * SD;
            float a = 0.f;
            for (int c = s + lane; c < e; c += 32) a += __ldcs(pr + c);
            acc[r] = a;
        }
    }

    // butterfly reduce all 8 accumulators
#pragma unroll
    for (int r = 0; r < ROWS_PER_WARP; r++) {
#pragma unroll
        for (int o = 16; o > 0; o >>= 1)
            acc[r] += __shfl_xor_sync(0xffffffffu, acc[r], o);
    }

    if (lane == 0) {
        const float inv_tau = 1.0f / 20.0f;
        size_t ob = (size_t)row0 * (size_t)K + g;
#pragma unroll
        for (int r = 0; r < ROWS_PER_WARP; r++)
            if (r < nrows) out[ob + (size_t)r * (size_t)K] = acc[r] * inv_tau;
    }
}

extern "C" void kernel_launch(void* const* d_in, const int* in_sizes, int n_in,
                              void* d_out, int out_size) {
    const float* x  = (const float*)d_in[0];
    const int*   gs = (const int*)d_in[1];

    int K = in_sizes[1];
    int B = out_size / K;
    int D = in_sizes[0] / B;

    float* out = (float*)d_out;

    dim3 grid(K, (B + ROWS_PER_BLOCK - 1) / ROWS_PER_BLOCK);
    pgs_fused_kernel<<<grid, 128>>>(x, gs, out, D, K, B);
}